// round 7
// baseline (speedup 1.0000x reference)
#include <cuda_runtime.h>
#include <cstdint>

// FactorizedTrilinear: B=4, Z=X=C=128, D=V=2 (dv=4), IN=512, R=256
// proj: P_k[b][dv][row][e] = x_k[b,row,dv,:] @ W_k + b_k   (g_P3 pre-rounded to tf32)
// tri:  out[b,z,x,c,dv] = sum_e (p1[z,e]*p2[x,e]) * p3[c,e] via mma.sync tf32.
//       CTA = M128(4z x 32x) x N128(c), K 4x64 double-buffered cp.async, dv loop.

#define NB  4
#define NZ  128
#define NIN 512
#define NR  256
#define NDV 4

__device__ __align__(16) float g_P1[NB * NDV * NZ * NR];
__device__ __align__(16) float g_P2[NB * NDV * NZ * NR];
__device__ __align__(16) float g_P3[NB * NDV * NZ * NR];

__device__ __forceinline__ uint32_t f2tf32(float f) {
    uint32_t u;
    asm("cvt.rna.tf32.f32 %0, %1;" : "=r"(u) : "f"(f));
    return u;
}
__device__ __forceinline__ void cp16(uint32_t dst, const void* src) {
    asm volatile("cp.async.cg.shared.global [%0], [%1], 16;"
                 :: "r"(dst), "l"(src) : "memory");
}
__device__ __forceinline__ void cp_commit() {
    asm volatile("cp.async.commit_group;" ::: "memory");
}
template <int N>
__device__ __forceinline__ void cp_wait() {
    asm volatile("cp.async.wait_group %0;" :: "n"(N) : "memory");
}

// ---------------------------------------------------------------------------
// Projection: grid (32, 4, 3), 256 threads. Block = 4 z rows, r = tid.
// k==2 (p3) stored pre-rounded to tf32 (B operand needs no cvt at use).
// ---------------------------------------------------------------------------
__global__ __launch_bounds__(256) void proj_kernel(
    const float* __restrict__ x1, const float* __restrict__ x2, const float* __restrict__ x3,
    const float* __restrict__ W1, const float* __restrict__ bb1,
    const float* __restrict__ W2, const float* __restrict__ bb2,
    const float* __restrict__ W3, const float* __restrict__ bb3)
{
    __shared__ __align__(16) float xs[4 * NIN * NDV];  // [z][e][dv] 32 KB
    __shared__ __align__(16) float ws[16 * NR];        // [e16][r]   16 KB

    const int z0 = blockIdx.x * 4;
    const int b  = blockIdx.y;
    const int k  = blockIdx.z;

    const float* x  = (k == 0) ? x1  : (k == 1) ? x2  : x3;
    const float* W  = (k == 0) ? W1  : (k == 1) ? W2  : W3;
    const float* bs = (k == 0) ? bb1 : (k == 1) ? bb2 : bb3;
    float*       P  = (k == 0) ? g_P1 : (k == 1) ? g_P2 : g_P3;

    const int tid = threadIdx.x;

    const float* xg = x + ((size_t)(b * NZ + z0)) * NDV * NIN;
#pragma unroll
    for (int i = 0; i < 32; i++) {
        int idx = i * 256 + tid;
        int e   = idx & (NIN - 1);
        int zdv = idx >> 9;
        xs[((zdv >> 2) * NIN + e) * NDV + (zdv & 3)] = xg[zdv * NIN + e];
    }

    float acc[4][NDV];
    {
        float bv = bs[tid];
#pragma unroll
        for (int z = 0; z < 4; z++)
#pragma unroll
            for (int dv = 0; dv < NDV; dv++) acc[z][dv] = bv;
    }

    for (int ec = 0; ec < NIN / 16; ec++) {
        __syncthreads();
        const float4* wg = (const float4*)(W + ec * 16 * NR);
        float4* ws4 = (float4*)ws;
#pragma unroll
        for (int i = 0; i < 4; i++) ws4[i * 256 + tid] = wg[i * 256 + tid];
        __syncthreads();

#pragma unroll
        for (int e16 = 0; e16 < 16; e16++) {
            float w = ws[e16 * NR + tid];
            int e = ec * 16 + e16;
#pragma unroll
            for (int z = 0; z < 4; z++) {
                float4 xv = *(const float4*)&xs[(z * NIN + e) * NDV];
                acc[z][0] = fmaf(xv.x, w, acc[z][0]);
                acc[z][1] = fmaf(xv.y, w, acc[z][1]);
                acc[z][2] = fmaf(xv.z, w, acc[z][2]);
                acc[z][3] = fmaf(xv.w, w, acc[z][3]);
            }
        }
    }

#pragma unroll
    for (int z = 0; z < 4; z++)
#pragma unroll
        for (int dv = 0; dv < NDV; dv++) {
            float v = acc[z][dv];
            if (k == 2) v = __uint_as_float(f2tf32(v));
            P[((size_t)((b * NDV + dv) * NZ + z0 + z)) * NR + tid] = v;
        }
}

// ---------------------------------------------------------------------------
// Trilinear. Grid (32, 4, 4): zq x xq x b. CTA: M=128(4z x 32x), N=128(c).
// 8 warps = 4M x 2N; warp tile M32 x N64 (2 m-tiles x 8 n-tiles of m16n8k8).
// dv(4) x K-chunks(4 x 64), cp.async double-buffered. 64 fp32 acc / thread.
// ---------------------------------------------------------------------------
#define KC   64
#define KPAD 68
#define OFF_P1 0
#define OFF_P2 (4 * KPAD)                   // 272
#define OFF_P3 (OFF_P2 + 32 * KPAD)         // 2448
#define BUF_F  (OFF_P3 + 128 * KPAD)        // 11152 floats / buffer
#define SMEM_BYTES (2 * BUF_F * 4)          // 89216

__global__ __launch_bounds__(256, 2) void tri_mma_kernel(float* __restrict__ out)
{
    extern __shared__ __align__(16) float sm[];

    const int tid  = threadIdx.x;
    const int wid  = tid >> 5;
    const int lane = tid & 31;
    const int grp  = lane >> 2;
    const int thr4 = lane & 3;

    const int zq = blockIdx.x;
    const int xq = blockIdx.y;
    const int b  = blockIdx.z;

    const int wm = (wid & 3) * 32;     // warp M offset (rows wm..wm+31)
    const int n0 = (wid >> 2) * 64;    // warp N offset
    const int zl = wid & 3;            // z row within CTA tile (uniform per warp)

    const uint32_t smu = (uint32_t)__cvta_generic_to_shared(sm);

    // stage s: dv = s>>2, ck = s&3, buffer = s&1
#define STAGE_FILL(s_)                                                          \
    {                                                                           \
        const int dv_ = (s_) >> 2, ck_ = (s_) & 3;                              \
        const uint32_t base = smu + ((s_) & 1) * (BUF_F * 4);                   \
        const float* p1b = g_P1 + ((size_t)((b * NDV + dv_) * NZ + zq * 4)) * NR + ck_ * KC;  \
        const float* p2b = g_P2 + ((size_t)((b * NDV + dv_) * NZ + xq * 32)) * NR + ck_ * KC; \
        const float* p3b = g_P3 + ((size_t)((b * NDV + dv_) * NZ)) * NR + ck_ * KC;           \
        if (tid < 64) {                                                         \
            int r = tid >> 4, q = tid & 15;                                     \
            cp16(base + (OFF_P1 + r * KPAD + q * 4) * 4, p1b + r * NR + q * 4); \
        }                                                                       \
        _Pragma("unroll")                                                       \
        for (int i = 0; i < 2; i++) {                                           \
            int g = i * 256 + tid, r = g >> 4, q = g & 15;                      \
            cp16(base + (OFF_P2 + r * KPAD + q * 4) * 4, p2b + r * NR + q * 4); \
        }                                                                       \
        _Pragma("unroll")                                                       \
        for (int i = 0; i < 8; i++) {                                           \
            int g = i * 256 + tid, r = g >> 4, q = g & 15;                      \
            cp16(base + (OFF_P3 + r * KPAD + q * 4) * 4, p3b + r * NR + q * 4); \
        }                                                                       \
    }

    float d[2][8][4];

    STAGE_FILL(0);
    cp_commit();

    for (int s = 0; s < 16; s++) {
        const int dv = s >> 2, ck = s & 3;
        if (s + 1 < 16) {
            STAGE_FILL(s + 1);
            cp_commit();
            cp_wait<1>();
        } else {
            cp_wait<0>();
        }
        __syncthreads();

        if (ck == 0) {
#pragma unroll
            for (int t = 0; t < 2; t++)
#pragma unroll
                for (int j = 0; j < 8; j++)
#pragma unroll
                    for (int i = 0; i < 4; i++) d[t][j][i] = 0.0f;
        }

        const float* p1s = sm + (s & 1) * BUF_F + OFF_P1;
        const float* p2s = sm + (s & 1) * BUF_F + OFF_P2;
        const float* p3s = sm + (s & 1) * BUF_F + OFF_P3;

#pragma unroll
        for (int kk = 0; kk < KC / 8; kk++) {
            const int k = kk * 8 + thr4;

            const float p1v0 = p1s[zl * KPAD + k];
            const float p1v1 = p1s[zl * KPAD + k + 4];

            uint32_t a[2][4];
#pragma unroll
            for (int t = 0; t < 2; t++) {
                const int x0 = 16 * t + grp;   // warp-local x for m-tile t
                float v00 = p2s[x0 * KPAD + k];
                float v10 = p2s[(x0 + 8) * KPAD + k];
                float v01 = p2s[x0 * KPAD + k + 4];
                float v11 = p2s[(x0 + 8) * KPAD + k + 4];
                a[t][0] = f2tf32(p1v0 * v00);
                a[t][1] = f2tf32(p1v0 * v10);
                a[t][2] = f2tf32(p1v1 * v01);
                a[t][3] = f2tf32(p1v1 * v11);
            }
#pragma unroll
            for (int j = 0; j < 8; j++) {
                const int c = n0 + j * 8 + grp;
                uint32_t b0 = __float_as_uint(p3s[c * KPAD + k]);
                uint32_t b1 = __float_as_uint(p3s[c * KPAD + k + 4]);
#pragma unroll
                for (int t = 0; t < 2; t++)
                    asm volatile(
                        "mma.sync.aligned.m16n8k8.row.col.f32.tf32.tf32.f32 "
                        "{%0,%1,%2,%3}, {%4,%5,%6,%7}, {%8,%9}, {%0,%1,%2,%3};"
                        : "+f"(d[t][j][0]), "+f"(d[t][j][1]),
                          "+f"(d[t][j][2]), "+f"(d[t][j][3])
                        : "r"(a[t][0]), "r"(a[t][1]), "r"(a[t][2]), "r"(a[t][3]),
                          "r"(b0), "r"(b1));
            }
        }

        if (ck == 3) {
            // Epilogue for this dv.
            const int z0g = zq * 4, x0g = xq * 32;
#pragma unroll
            for (int t = 0; t < 2; t++) {
                const int xa = 16 * t + grp;          // m0 & 31
                const size_t rb0 = ((((size_t)(b * NZ + z0g + zl)) * NZ
                                     + x0g + xa) * NZ) * NDV + dv;
                const size_t rb1 = ((((size_t)(b * NZ + z0g + zl)) * NZ
                                     + x0g + xa + 8) * NZ) * NDV + dv;
#pragma unroll
                for (int j = 0; j < 8; j++) {
                    const int cg = n0 + j * 8 + thr4 * 2;
                    out[rb0 + (size_t)cg * NDV]       = d[t][j][0];
                    out[rb0 + (size_t)(cg + 1) * NDV] = d[t][j][1];
                    out[rb1 + (size_t)cg * NDV]       = d[t][j][2];
                    out[rb1 + (size_t)(cg + 1) * NDV] = d[t][j][3];
                }
            }
        }
        __syncthreads();
    }
#undef STAGE_FILL
}

// ---------------------------------------------------------------------------
extern "C" void kernel_launch(void* const* d_in, const int* in_sizes, int n_in,
                              void* d_out, int out_size)
{
    (void)in_sizes; (void)n_in; (void)out_size;
    const float* x1 = (const float*)d_in[0];
    const float* x2 = (const float*)d_in[1];
    const float* x3 = (const float*)d_in[2];
    const float* W1 = (const float*)d_in[3];
    const float* b1 = (const float*)d_in[4];
    const float* W2 = (const float*)d_in[5];
    const float* b2 = (const float*)d_in[6];
    const float* W3 = (const float*)d_in[7];
    const float* b3 = (const float*)d_in[8];
    float* out = (float*)d_out;

    static int attr_done = 0;
    if (!attr_done) {
        cudaFuncSetAttribute(tri_mma_kernel,
                             cudaFuncAttributeMaxDynamicSharedMemorySize, SMEM_BYTES);
        attr_done = 1;
    }

    proj_kernel<<<dim3(32, NB, 3), 256>>>(x1, x2, x3, W1, b1, W2, b2, W3, b3);
    tri_mma_kernel<<<dim3(32, 4, NB), 256, SMEM_BYTES>>>(out);
}

// round 8
// speedup vs baseline: 1.0362x; 1.0362x over previous
#include <cuda_runtime.h>
#include <cstdint>

// FactorizedTrilinear: B=4, Z=X=C=128, D=V=2 (dv=4), IN=512, R=256
// proj: P_k[b][dv][row][e] = x_k[b,row,dv,:] @ W_k + b_k   (g_P3 pre-rounded to tf32)
// tri:  out[b,z,x,c,dv] = sum_e (p1[z,e]*p2[x,e]) * p3[c,e] via mma.sync tf32.
//       CTA = M128(4z x 32x) x N64(c), KC=64 double-buffered cp.async, 3 CTAs/SM.

#define NB  4
#define NZ  128
#define NIN 512
#define NR  256
#define NDV 4

__device__ __align__(16) float g_P1[NB * NDV * NZ * NR];
__device__ __align__(16) float g_P2[NB * NDV * NZ * NR];
__device__ __align__(16) float g_P3[NB * NDV * NZ * NR];

__device__ __forceinline__ uint32_t f2tf32(float f) {
    uint32_t u;
    asm("cvt.rna.tf32.f32 %0, %1;" : "=r"(u) : "f"(f));
    return u;
}
__device__ __forceinline__ void cp16(uint32_t dst, const void* src) {
    asm volatile("cp.async.cg.shared.global [%0], [%1], 16;"
                 :: "r"(dst), "l"(src) : "memory");
}
__device__ __forceinline__ void cp_commit() {
    asm volatile("cp.async.commit_group;" ::: "memory");
}
template <int N>
__device__ __forceinline__ void cp_wait() {
    asm volatile("cp.async.wait_group %0;" :: "n"(N) : "memory");
}

// ---------------------------------------------------------------------------
// Projection: grid (16, 4, 3), 256 threads, 80 KB dynamic smem.
// Block = 8 z rows (ZG), r = tid. W streamed once per block in 16-e chunks
// (W refetch halved vs R7: 192 blocks x 512 KB = 98 MB).
// k==2 (p3) stored pre-rounded to tf32.
// ---------------------------------------------------------------------------
#define ZG 8
#define PROJ_SMEM ((ZG * NIN * NDV + 16 * NR) * 4)   // 64KB + 16KB

__global__ __launch_bounds__(256) void proj_kernel(
    const float* __restrict__ x1, const float* __restrict__ x2, const float* __restrict__ x3,
    const float* __restrict__ W1, const float* __restrict__ bb1,
    const float* __restrict__ W2, const float* __restrict__ bb2,
    const float* __restrict__ W3, const float* __restrict__ bb3)
{
    extern __shared__ __align__(16) float psm[];
    float* xs = psm;                    // [z][e][dv]  ZG*512*4
    float* ws = psm + ZG * NIN * NDV;   // [e16][r]    16*256

    const int z0 = blockIdx.x * ZG;
    const int b  = blockIdx.y;
    const int k  = blockIdx.z;

    const float* x  = (k == 0) ? x1  : (k == 1) ? x2  : x3;
    const float* W  = (k == 0) ? W1  : (k == 1) ? W2  : W3;
    const float* bs = (k == 0) ? bb1 : (k == 1) ? bb2 : bb3;
    float*       P  = (k == 0) ? g_P1 : (k == 1) ? g_P2 : g_P3;

    const int tid = threadIdx.x;

    // Fill xs: ZG*4 rows of 512 e (transpose e<->dv while storing).
    const float* xg = x + ((size_t)(b * NZ + z0)) * NDV * NIN;
#pragma unroll
    for (int i = 0; i < ZG * 8; i++) {
        int idx = i * 256 + tid;
        int e   = idx & (NIN - 1);
        int zdv = idx >> 9;                       // 0..ZG*4-1
        xs[((zdv >> 2) * NIN + e) * NDV + (zdv & 3)] = xg[zdv * NIN + e];
    }

    float acc[ZG][NDV];
    {
        float bv = bs[tid];
#pragma unroll
        for (int z = 0; z < ZG; z++)
#pragma unroll
            for (int dv = 0; dv < NDV; dv++) acc[z][dv] = bv;
    }

    for (int ec = 0; ec < NIN / 16; ec++) {
        __syncthreads();
        const float4* wg = (const float4*)(W + ec * 16 * NR);
        float4* ws4 = (float4*)ws;
#pragma unroll
        for (int i = 0; i < 4; i++) ws4[i * 256 + tid] = wg[i * 256 + tid];
        __syncthreads();

#pragma unroll
        for (int e16 = 0; e16 < 16; e16++) {
            float w = ws[e16 * NR + tid];
            int e = ec * 16 + e16;
#pragma unroll
            for (int z = 0; z < ZG; z++) {
                float4 xv = *(const float4*)&xs[(z * NIN + e) * NDV];
                acc[z][0] = fmaf(xv.x, w, acc[z][0]);
                acc[z][1] = fmaf(xv.y, w, acc[z][1]);
                acc[z][2] = fmaf(xv.z, w, acc[z][2]);
                acc[z][3] = fmaf(xv.w, w, acc[z][3]);
            }
        }
    }

#pragma unroll
    for (int z = 0; z < ZG; z++)
#pragma unroll
        for (int dv = 0; dv < NDV; dv++) {
            float v = acc[z][dv];
            if (k == 2) v = __uint_as_float(f2tf32(v));
            P[((size_t)((b * NDV + dv) * NZ + z0 + z)) * NR + tid] = v;
        }
}

// ---------------------------------------------------------------------------
// Trilinear. Grid (32, 8, 4): zq x [xq|ch] x b. CTA: M=128(4z x 32x), N=64(c).
// 8 warps = 4M x 2N; warp tile M32 x N32 (2 m-tiles x 4 n-tiles m16n8k8).
// dv(4) x ck(4 x KC=64), cp.async double-buffered, 54.4 KB smem -> 3 CTAs/SM.
// ---------------------------------------------------------------------------
#define KC   64
#define KPAD 68
#define OFF_P1 0
#define OFF_P2 (4 * KPAD)                   // 272
#define OFF_P3 (OFF_P2 + 32 * KPAD)         // 2448
#define BUF_F  (OFF_P3 + 64 * KPAD)         // 6800 floats / buffer
#define SMEM_BYTES (2 * BUF_F * 4)          // 54400

__global__ __launch_bounds__(256, 3) void tri_mma_kernel(float* __restrict__ out)
{
    extern __shared__ __align__(16) float sm[];

    const int tid  = threadIdx.x;
    const int wid  = tid >> 5;
    const int lane = tid & 31;
    const int grp  = lane >> 2;
    const int thr4 = lane & 3;

    const int zq = blockIdx.x;
    const int xq = blockIdx.y & 3;
    const int ch = blockIdx.y >> 2;
    const int b  = blockIdx.z;

    const int wm = (wid & 3) * 32;     // warp M offset (rows wm..wm+31)
    const int n0 = (wid >> 2) * 32;    // warp N offset
    const int zl = wid & 3;            // z row within CTA tile (uniform per warp)

    const uint32_t smu = (uint32_t)__cvta_generic_to_shared(sm);

    // stage s: dv = s>>2, ck = s&3, buffer = s&1
#define STAGE_FILL(s_)                                                          \
    {                                                                           \
        const int dv_ = (s_) >> 2, ck_ = (s_) & 3;                              \
        const uint32_t base = smu + ((s_) & 1) * (BUF_F * 4);                   \
        const float* p1b = g_P1 + ((size_t)((b * NDV + dv_) * NZ + zq * 4)) * NR + ck_ * KC;  \
        const float* p2b = g_P2 + ((size_t)((b * NDV + dv_) * NZ + xq * 32)) * NR + ck_ * KC; \
        const float* p3b = g_P3 + ((size_t)((b * NDV + dv_) * NZ + ch * 64)) * NR + ck_ * KC; \
        if (tid < 64) {                                                         \
            int r = tid >> 4, q = tid & 15;                                     \
            cp16(base + (OFF_P1 + r * KPAD + q * 4) * 4, p1b + r * NR + q * 4); \
        }                                                                       \
        _Pragma("unroll")                                                       \
        for (int i = 0; i < 2; i++) {                                           \
            int g = i * 256 + tid, r = g >> 4, q = g & 15;                      \
            cp16(base + (OFF_P2 + r * KPAD + q * 4) * 4, p2b + r * NR + q * 4); \
        }                                                                       \
        _Pragma("unroll")                                                       \
        for (int i = 0; i < 4; i++) {                                           \
            int g = i * 256 + tid, r = g >> 4, q = g & 15;                      \
            cp16(base + (OFF_P3 + r * KPAD + q * 4) * 4, p3b + r * NR + q * 4); \
        }                                                                       \
    }

    float d[2][4][4];

    STAGE_FILL(0);
    cp_commit();

    for (int s = 0; s < 16; s++) {
        const int dv = s >> 2, ck = s & 3;
        if (s + 1 < 16) {
            STAGE_FILL(s + 1);
            cp_commit();
            cp_wait<1>();
        } else {
            cp_wait<0>();
        }
        __syncthreads();

        if (ck == 0) {
#pragma unroll
            for (int t = 0; t < 2; t++)
#pragma unroll
                for (int j = 0; j < 4; j++)
#pragma unroll
                    for (int i = 0; i < 4; i++) d[t][j][i] = 0.0f;
        }

        const float* p1s = sm + (s & 1) * BUF_F + OFF_P1;
        const float* p2s = sm + (s & 1) * BUF_F + OFF_P2;
        const float* p3s = sm + (s & 1) * BUF_F + OFF_P3;

#pragma unroll
        for (int kk = 0; kk < KC / 8; kk++) {
            const int k = kk * 8 + thr4;

            const float p1v0 = p1s[zl * KPAD + k];
            const float p1v1 = p1s[zl * KPAD + k + 4];

            uint32_t a[2][4];
#pragma unroll
            for (int t = 0; t < 2; t++) {
                const int x0 = 16 * t + grp;
                float v00 = p2s[x0 * KPAD + k];
                float v10 = p2s[(x0 + 8) * KPAD + k];
                float v01 = p2s[x0 * KPAD + k + 4];
                float v11 = p2s[(x0 + 8) * KPAD + k + 4];
                a[t][0] = f2tf32(p1v0 * v00);
                a[t][1] = f2tf32(p1v0 * v10);
                a[t][2] = f2tf32(p1v1 * v01);
                a[t][3] = f2tf32(p1v1 * v11);
            }
            uint32_t bf[4][2];
#pragma unroll
            for (int j = 0; j < 4; j++) {
                const int c = n0 + j * 8 + grp;
                bf[j][0] = __float_as_uint(p3s[c * KPAD + k]);
                bf[j][1] = __float_as_uint(p3s[c * KPAD + k + 4]);
            }
#pragma unroll
            for (int t = 0; t < 2; t++)
#pragma unroll
                for (int j = 0; j < 4; j++)
                    asm volatile(
                        "mma.sync.aligned.m16n8k8.row.col.f32.tf32.tf32.f32 "
                        "{%0,%1,%2,%3}, {%4,%5,%6,%7}, {%8,%9}, {%0,%1,%2,%3};"
                        : "+f"(d[t][j][0]), "+f"(d[t][j][1]),
                          "+f"(d[t][j][2]), "+f"(d[t][j][3])
                        : "r"(a[t][0]), "r"(a[t][1]), "r"(a[t][2]), "r"(a[t][3]),
                          "r"(bf[j][0]), "r"(bf[j][1]));
        }

        if (ck == 3) {
            // Epilogue for this dv.
            const int z0g = zq * 4, x0g = xq * 32;
#pragma unroll
            for (int t = 0; t < 2; t++) {
                const int xa = 16 * t + grp;
                const size_t rb0 = ((((size_t)(b * NZ + z0g + zl)) * NZ
                                     + x0g + xa) * NZ) * NDV + dv;
                const size_t rb1 = ((((size_t)(b * NZ + z0g + zl)) * NZ
                                     + x0g + xa + 8) * NZ) * NDV + dv;
#pragma unroll
                for (int j = 0; j < 4; j++) {
                    const int cg = ch * 64 + n0 + j * 8 + thr4 * 2;
                    out[rb0 + (size_t)cg * NDV]       = d[t][j][0];
                    out[rb0 + (size_t)(cg + 1) * NDV] = d[t][j][1];
                    out[rb1 + (size_t)cg * NDV]       = d[t][j][2];
                    out[rb1 + (size_t)(cg + 1) * NDV] = d[t][j][3];
                }
            }
        }
        __syncthreads();
    }
#undef STAGE_FILL
}

// ---------------------------------------------------------------------------
extern "C" void kernel_launch(void* const* d_in, const int* in_sizes, int n_in,
                              void* d_out, int out_size)
{
    (void)in_sizes; (void)n_in; (void)out_size;
    const float* x1 = (const float*)d_in[0];
    const float* x2 = (const float*)d_in[1];
    const float* x3 = (const float*)d_in[2];
    const float* W1 = (const float*)d_in[3];
    const float* b1 = (const float*)d_in[4];
    const float* W2 = (const float*)d_in[5];
    const float* b2 = (const float*)d_in[6];
    const float* W3 = (const float*)d_in[7];
    const float* b3 = (const float*)d_in[8];
    float* out = (float*)d_out;

    static int attr_done = 0;
    if (!attr_done) {
        cudaFuncSetAttribute(tri_mma_kernel,
                             cudaFuncAttributeMaxDynamicSharedMemorySize, SMEM_BYTES);
        cudaFuncSetAttribute(proj_kernel,
                             cudaFuncAttributeMaxDynamicSharedMemorySize, PROJ_SMEM);
        attr_done = 1;
    }

    proj_kernel<<<dim3(16, NB, 3), 256, PROJ_SMEM>>>(x1, x2, x3, W1, b1, W2, b2, W3, b3);
    tri_mma_kernel<<<dim3(32, 8, NB), 256, SMEM_BYTES>>>(out);
}

// round 10
// speedup vs baseline: 1.1297x; 1.0902x over previous
#include <cuda_runtime.h>
#include <cstdint>

// FactorizedTrilinear: B=4, Z=X=C=128, D=V=2 (dv=4), IN=512, R=256
// proj: P_k[b][dv][row][e] = x_k[b,row,dv,:] @ W_k + b_k   (g_P3 pre-rounded to tf32)
// tri:  out[b,z,x,c,dv] = sum_e (p1[z,e]*p2[x,e]) * p3[c,e] via mma.sync tf32.
//       CTA = M128(4z x 32x) x N64(c), KC=128 double-buffered cp.async,
//       per-warp software-pipelined fragment loads (2-deep register buffer).

#define NB  4
#define NZ  128
#define NIN 512
#define NR  256
#define NDV 4

__device__ __align__(16) float g_P1[NB * NDV * NZ * NR];
__device__ __align__(16) float g_P2[NB * NDV * NZ * NR];
__device__ __align__(16) float g_P3[NB * NDV * NZ * NR];

__device__ __forceinline__ uint32_t f2tf32(float f) {
    uint32_t u;
    asm("cvt.rna.tf32.f32 %0, %1;" : "=r"(u) : "f"(f));
    return u;
}
__device__ __forceinline__ void cp16(uint32_t dst, const void* src) {
    asm volatile("cp.async.cg.shared.global [%0], [%1], 16;"
                 :: "r"(dst), "l"(src) : "memory");
}
__device__ __forceinline__ void cp_commit() {
    asm volatile("cp.async.commit_group;" ::: "memory");
}
template <int N>
__device__ __forceinline__ void cp_wait() {
    asm volatile("cp.async.wait_group %0;" :: "n"(N) : "memory");
}

// ---------------------------------------------------------------------------
// Projection: grid (32, 4, 3), 256 threads, 64 KB dynamic smem.
// Block = 4 z rows, r = tid. W streamed in 16-e chunks, cp.async double-buffered.
// k==2 (p3) stored pre-rounded to tf32.
// ---------------------------------------------------------------------------
#define PROJ_SMEM ((4 * NIN * NDV + 2 * 16 * NR) * 4)   // 32KB + 32KB

__global__ __launch_bounds__(256) void proj_kernel(
    const float* __restrict__ x1, const float* __restrict__ x2, const float* __restrict__ x3,
    const float* __restrict__ W1, const float* __restrict__ bb1,
    const float* __restrict__ W2, const float* __restrict__ bb2,
    const float* __restrict__ W3, const float* __restrict__ bb3)
{
    extern __shared__ __align__(16) float psm[];
    float* xs = psm;                      // [z][e][dv] 4*512*4 floats
    float* ws = psm + 4 * NIN * NDV;      // 2 x [e16][r] 16*256 floats each

    const int z0 = blockIdx.x * 4;
    const int b  = blockIdx.y;
    const int k  = blockIdx.z;

    const float* x  = (k == 0) ? x1  : (k == 1) ? x2  : x3;
    const float* W  = (k == 0) ? W1  : (k == 1) ? W2  : W3;
    const float* bs = (k == 0) ? bb1 : (k == 1) ? bb2 : bb3;
    float*       P  = (k == 0) ? g_P1 : (k == 1) ? g_P2 : g_P3;

    const int tid = threadIdx.x;
    const uint32_t wsu = (uint32_t)__cvta_generic_to_shared(ws);

    // Fill xs: 16 rows of 512 e (transpose e<->dv while storing).
    const float* xg = x + ((size_t)(b * NZ + z0)) * NDV * NIN;
#pragma unroll
    for (int i = 0; i < 32; i++) {
        int idx = i * 256 + tid;
        int e   = idx & (NIN - 1);
        int zdv = idx >> 9;
        xs[((zdv >> 2) * NIN + e) * NDV + (zdv & 3)] = xg[zdv * NIN + e];
    }

#define WFILL(ec_)                                                      \
    {                                                                   \
        const float4* wg = (const float4*)(W + (ec_) * 16 * NR);        \
        uint32_t base = wsu + ((ec_) & 1) * (16 * NR * 4);              \
        _Pragma("unroll")                                               \
        for (int i = 0; i < 4; i++)                                     \
            cp16(base + (i * 256 + tid) * 16, wg + i * 256 + tid);      \
    }

    float acc[4][NDV];
    {
        float bv = bs[tid];
#pragma unroll
        for (int z = 0; z < 4; z++)
#pragma unroll
            for (int dv = 0; dv < NDV; dv++) acc[z][dv] = bv;
    }

    WFILL(0);
    cp_commit();

    for (int ec = 0; ec < NIN / 16; ec++) {
        if (ec + 1 < NIN / 16) {
            WFILL(ec + 1);
            cp_commit();
            cp_wait<1>();
        } else {
            cp_wait<0>();
        }
        __syncthreads();   // ws chunk visible (first iter also covers xs)

        const float* w = ws + (ec & 1) * 16 * NR;
#pragma unroll
        for (int e16 = 0; e16 < 16; e16++) {
            float wv = w[e16 * NR + tid];
            int e = ec * 16 + e16;
#pragma unroll
            for (int z = 0; z < 4; z++) {
                float4 xv = *(const float4*)&xs[(z * NIN + e) * NDV];
                acc[z][0] = fmaf(xv.x, wv, acc[z][0]);
                acc[z][1] = fmaf(xv.y, wv, acc[z][1]);
                acc[z][2] = fmaf(xv.z, wv, acc[z][2]);
                acc[z][3] = fmaf(xv.w, wv, acc[z][3]);
            }
        }
        __syncthreads();   // all reads of this ws buffer done before refill
    }
#undef WFILL

#pragma unroll
    for (int z = 0; z < 4; z++)
#pragma unroll
        for (int dv = 0; dv < NDV; dv++) {
            float v = acc[z][dv];
            if (k == 2) v = __uint_as_float(f2tf32(v));
            P[((size_t)((b * NDV + dv) * NZ + z0 + z)) * NR + tid] = v;
        }
}

// ---------------------------------------------------------------------------
// Trilinear. Grid (32, 8, 4): zq x [xq|ch] x b. CTA: M=128(4z x 32x), N=64(c).
// 8 warps = 4M x 2N; warp tile M32 x N32 (2 m-tiles x 4 n-tiles m16n8k8).
// dv(4) x ck(2 x KC=128), cp.async double-buffered smem, 105.6 KB, 2 CTAs/SM.
// Fragment loads software-pipelined 2-deep across k-steps.
// ---------------------------------------------------------------------------
#define KC   128
#define KPAD 132
#define OFF_P1 0
#define OFF_P2 (4 * KPAD)                    // 528
#define OFF_P3 (OFF_P2 + 32 * KPAD)          // 4752
#define BUF_F  (OFF_P3 + 64 * KPAD)          // 13200 floats / buffer
#define SMEM_BYTES (2 * BUF_F * 4)           // 105600

__global__ __launch_bounds__(256, 2) void tri_mma_kernel(float* __restrict__ out)
{
    extern __shared__ __align__(16) float sm[];

    const int tid  = threadIdx.x;
    const int wid  = tid >> 5;
    const int lane = tid & 31;
    const int grp  = lane >> 2;
    const int thr4 = lane & 3;

    const int zq = blockIdx.x;
    const int xq = blockIdx.y & 3;
    const int ch = blockIdx.y >> 2;
    const int b  = blockIdx.z;

    const int n0 = (wid >> 2) * 32;    // warp N offset
    const int zl = wid & 3;            // z row within CTA tile (uniform per warp)

    const uint32_t smu = (uint32_t)__cvta_generic_to_shared(sm);

    // stage s: dv = s>>1, ck = s&1, buffer = s&1
#define STAGE_FILL(s_)                                                          \
    {                                                                           \
        const int dv_ = (s_) >> 1, ck_ = (s_) & 1;                              \
        const uint32_t base = smu + ((s_) & 1) * (BUF_F * 4);                   \
        const float* p1b = g_P1 + ((size_t)((b * NDV + dv_) * NZ + zq * 4)) * NR + ck_ * KC;  \
        const float* p2b = g_P2 + ((size_t)((b * NDV + dv_) * NZ + xq * 32)) * NR + ck_ * KC; \
        const float* p3b = g_P3 + ((size_t)((b * NDV + dv_) * NZ + ch * 64)) * NR + ck_ * KC; \
        if (tid < 128) {                                                        \
            int r = tid >> 5, q = tid & 31;                                     \
            cp16(base + (OFF_P1 + r * KPAD + q * 4) * 4, p1b + r * NR + q * 4); \
        }                                                                       \
        _Pragma("unroll")                                                       \
        for (int i = 0; i < 4; i++) {                                           \
            int g = i * 256 + tid, r = g >> 5, q = g & 31;                      \
            cp16(base + (OFF_P2 + r * KPAD + q * 4) * 4, p2b + r * NR + q * 4); \
        }                                                                       \
        _Pragma("unroll")                                                       \
        for (int i = 0; i < 8; i++) {                                           \
            int g = i * 256 + tid, r = g >> 5, q = g & 31;                      \
            cp16(base + (OFF_P3 + r * KPAD + q * 4) * 4, p3b + r * NR + q * 4); \
        }                                                                       \
    }

    // Raw fragment loads for one k-step into register buffer B_.
#define LOADK(B_, KV_)                                                          \
    {                                                                           \
        const int k_ = (KV_);                                                   \
        rp1[B_][0] = p1s[zl * KPAD + k_];                                       \
        rp1[B_][1] = p1s[zl * KPAD + k_ + 4];                                   \
        _Pragma("unroll")                                                       \
        for (int t = 0; t < 2; t++) {                                           \
            const int x0 = 16 * t + grp;                                        \
            rp2[B_][t][0] = p2s[x0 * KPAD + k_];                                \
            rp2[B_][t][1] = p2s[(x0 + 8) * KPAD + k_];                          \
            rp2[B_][t][2] = p2s[x0 * KPAD + k_ + 4];                            \
            rp2[B_][t][3] = p2s[(x0 + 8) * KPAD + k_ + 4];                      \
        }                                                                       \
        _Pragma("unroll")                                                       \
        for (int j = 0; j < 4; j++) {                                           \
            const int c = n0 + j * 8 + grp;                                     \
            rp3[B_][j][0] = p3s[c * KPAD + k_];                                 \
            rp3[B_][j][1] = p3s[c * KPAD + k_ + 4];                             \
        }                                                                       \
    }

    float d[2][4][4];
    float rp1[2][2], rp2[2][2][4], rp3[2][4][2];

    STAGE_FILL(0);
    cp_commit();

    for (int s = 0; s < 8; s++) {
        const int dv = s >> 1, ck = s & 1;
        if (s + 1 < 8) {
            STAGE_FILL(s + 1);
            cp_commit();
            cp_wait<1>();
        } else {
            cp_wait<0>();
        }
        __syncthreads();

        if (ck == 0) {
#pragma unroll
            for (int t = 0; t < 2; t++)
#pragma unroll
                for (int j = 0; j < 4; j++)
#pragma unroll
                    for (int i = 0; i < 4; i++) d[t][j][i] = 0.0f;
        }

        const float* p1s = sm + (s & 1) * BUF_F + OFF_P1;
        const float* p2s = sm + (s & 1) * BUF_F + OFF_P2;
        const float* p3s = sm + (s & 1) * BUF_F + OFF_P3;

        LOADK(0, thr4);
#pragma unroll
        for (int kk = 0; kk < KC / 8; kk++) {
            const int cur = kk & 1;
            if (kk + 1 < KC / 8) LOADK((kk + 1) & 1, (kk + 1) * 8 + thr4);

            uint32_t a[2][4];
#pragma unroll
            for (int t = 0; t < 2; t++) {
                a[t][0] = f2tf32(rp1[cur][0] * rp2[cur][t][0]);
                a[t][1] = f2tf32(rp1[cur][0] * rp2[cur][t][1]);
                a[t][2] = f2tf32(rp1[cur][1] * rp2[cur][t][2]);
                a[t][3] = f2tf32(rp1[cur][1] * rp2[cur][t][3]);
            }
#pragma unroll
            for (int t = 0; t < 2; t++)
#pragma unroll
                for (int j = 0; j < 4; j++)
                    asm volatile(
                        "mma.sync.aligned.m16n8k8.row.col.f32.tf32.tf32.f32 "
                        "{%0,%1,%2,%3}, {%4,%5,%6,%7}, {%8,%9}, {%0,%1,%2,%3};"
                        : "+f"(d[t][j][0]), "+f"(d[t][j][1]),
                          "+f"(d[t][j][2]), "+f"(d[t][j][3])
                        : "r"(a[t][0]), "r"(a[t][1]), "r"(a[t][2]), "r"(a[t][3]),
                          "r"(__float_as_uint(rp3[cur][j][0])),
                          "r"(__float_as_uint(rp3[cur][j][1])));
        }

        if (ck == 1) {
            // Epilogue for this dv.
            const int z0g = zq * 4, x0g = xq * 32;
#pragma unroll
            for (int t = 0; t < 2; t++) {
                const int xa = 16 * t + grp;
                const size_t rb0 = ((((size_t)(b * NZ + z0g + zl)) * NZ
                                     + x0g + xa) * NZ) * NDV + dv;
                const size_t rb1 = ((((size_t)(b * NZ + z0g + zl)) * NZ
                                     + x0g + xa + 8) * NZ) * NDV + dv;
#pragma unroll
                for (int j = 0; j < 4; j++) {
                    const int cg = ch * 64 + n0 + j * 8 + thr4 * 2;
                    out[rb0 + (size_t)cg * NDV]       = d[t][j][0];
                    out[rb0 + (size_t)(cg + 1) * NDV] = d[t][j][1];
                    out[rb1 + (size_t)cg * NDV]       = d[t][j][2];
                    out[rb1 + (size_t)(cg + 1) * NDV] = d[t][j][3];
                }
            }
        }
        __syncthreads();
    }
#undef STAGE_FILL
#undef LOADK
}

// ---------------------------------------------------------------------------
extern "C" void kernel_launch(void* const* d_in, const int* in_sizes, int n_in,
                              void* d_out, int out_size)
{
    (void)in_sizes; (void)n_in; (void)out_size;
    const float* x1 = (const float*)d_in[0];
    const float* x2 = (const float*)d_in[1];
    const float* x3 = (const float*)d_in[2];
    const float* W1 = (const float*)d_in[3];
    const float* b1 = (const float*)d_in[4];
    const float* W2 = (const float*)d_in[5];
    const float* b2 = (const float*)d_in[6];
    const float* W3 = (const float*)d_in[7];
    const float* b3 = (const float*)d_in[8];
    float* out = (float*)d_out;

    static int attr_done = 0;
    if (!attr_done) {
        cudaFuncSetAttribute(tri_mma_kernel,
                             cudaFuncAttributeMaxDynamicSharedMemorySize, SMEM_BYTES);
        cudaFuncSetAttribute(proj_kernel,
                             cudaFuncAttributeMaxDynamicSharedMemorySize, PROJ_SMEM);
        attr_done = 1;
    }

    proj_kernel<<<dim3(32, NB, 3), 256, PROJ_SMEM>>>(x1, x2, x3, W1, b1, W2, b2, W3, b3);
    tri_mma_kernel<<<dim3(32, 8, NB), 256, SMEM_BYTES>>>(out);
}

// round 11
// speedup vs baseline: 1.1439x; 1.0126x over previous
#include <cuda_runtime.h>
#include <cuda_fp16.h>
#include <cstdint>

// FactorizedTrilinear: B=4, Z=X=C=128, D=V=2 (dv=4), IN=512, R=256
// proj: P_k[b][dv][row][e] = x_k[b,row,dv,:] @ W_k + b_k
//       (p1,p2 stored fp32; p3 stored fp16 -> B operand of the MMA)
// tri:  out[b,z,x,c,dv] = sum_e (p1[z,e]*p2[x,e]) * p3[c,e] via
//       mma.sync.m16n8k16.f16 (A = fp16(p1*p2 product in fp32), fp32 accum).
//       CTA = M128(4z x 32x) x N64(c), KC=128 double-buffered cp.async.

#define NB  4
#define NZ  128
#define NIN 512
#define NR  256
#define NDV 4

__device__ __align__(16) float  g_P1[NB * NDV * NZ * NR];
__device__ __align__(16) float  g_P2[NB * NDV * NZ * NR];
__device__ __align__(16) __half g_P3h[NB * NDV * NZ * NR];

__device__ __forceinline__ void cp16(uint32_t dst, const void* src) {
    asm volatile("cp.async.cg.shared.global [%0], [%1], 16;"
                 :: "r"(dst), "l"(src) : "memory");
}
__device__ __forceinline__ void cp_commit() {
    asm volatile("cp.async.commit_group;" ::: "memory");
}
template <int N>
__device__ __forceinline__ void cp_wait() {
    asm volatile("cp.async.wait_group %0;" :: "n"(N) : "memory");
}
__device__ __forceinline__ uint32_t packh2(float lo, float hi) {
    __half2 h = __float22half2_rn(make_float2(lo, hi));
    return *(uint32_t*)&h;
}

// ---------------------------------------------------------------------------
// Projection: grid (32, 4, 3), 256 threads, 64 KB dynamic smem.
// Block = 4 z rows, r = tid. W streamed in 16-e chunks, cp.async double-buffered.
// k==2 (p3) stored as fp16.
// ---------------------------------------------------------------------------
#define PROJ_SMEM ((4 * NIN * NDV + 2 * 16 * NR) * 4)   // 32KB + 32KB

__global__ __launch_bounds__(256) void proj_kernel(
    const float* __restrict__ x1, const float* __restrict__ x2, const float* __restrict__ x3,
    const float* __restrict__ W1, const float* __restrict__ bb1,
    const float* __restrict__ W2, const float* __restrict__ bb2,
    const float* __restrict__ W3, const float* __restrict__ bb3)
{
    extern __shared__ __align__(16) float psm[];
    float* xs = psm;                      // [z][e][dv] 4*512*4 floats
    float* ws = psm + 4 * NIN * NDV;      // 2 x [e16][r] 16*256 floats each

    const int z0 = blockIdx.x * 4;
    const int b  = blockIdx.y;
    const int k  = blockIdx.z;

    const float* x  = (k == 0) ? x1  : (k == 1) ? x2  : x3;
    const float* W  = (k == 0) ? W1  : (k == 1) ? W2  : W3;
    const float* bs = (k == 0) ? bb1 : (k == 1) ? bb2 : bb3;

    const int tid = threadIdx.x;
    const uint32_t wsu = (uint32_t)__cvta_generic_to_shared(ws);

    const float* xg = x + ((size_t)(b * NZ + z0)) * NDV * NIN;
#pragma unroll
    for (int i = 0; i < 32; i++) {
        int idx = i * 256 + tid;
        int e   = idx & (NIN - 1);
        int zdv = idx >> 9;
        xs[((zdv >> 2) * NIN + e) * NDV + (zdv & 3)] = xg[zdv * NIN + e];
    }

#define WFILL(ec_)                                                      \
    {                                                                   \
        const float4* wg = (const float4*)(W + (ec_) * 16 * NR);        \
        uint32_t base = wsu + ((ec_) & 1) * (16 * NR * 4);              \
        _Pragma("unroll")                                               \
        for (int i = 0; i < 4; i++)                                     \
            cp16(base + (i * 256 + tid) * 16, wg + i * 256 + tid);      \
    }

    float acc[4][NDV];
    {
        float bv = bs[tid];
#pragma unroll
        for (int z = 0; z < 4; z++)
#pragma unroll
            for (int dv = 0; dv < NDV; dv++) acc[z][dv] = bv;
    }

    WFILL(0);
    cp_commit();

    for (int ec = 0; ec < NIN / 16; ec++) {
        if (ec + 1 < NIN / 16) {
            WFILL(ec + 1);
            cp_commit();
            cp_wait<1>();
        } else {
            cp_wait<0>();
        }
        __syncthreads();

        const float* w = ws + (ec & 1) * 16 * NR;
#pragma unroll
        for (int e16 = 0; e16 < 16; e16++) {
            float wv = w[e16 * NR + tid];
            int e = ec * 16 + e16;
#pragma unroll
            for (int z = 0; z < 4; z++) {
                float4 xv = *(const float4*)&xs[(z * NIN + e) * NDV];
                acc[z][0] = fmaf(xv.x, wv, acc[z][0]);
                acc[z][1] = fmaf(xv.y, wv, acc[z][1]);
                acc[z][2] = fmaf(xv.z, wv, acc[z][2]);
                acc[z][3] = fmaf(xv.w, wv, acc[z][3]);
            }
        }
        __syncthreads();
    }
#undef WFILL

#pragma unroll
    for (int z = 0; z < 4; z++)
#pragma unroll
        for (int dv = 0; dv < NDV; dv++) {
            size_t off = ((size_t)((b * NDV + dv) * NZ + z0 + z)) * NR + tid;
            if (k == 2) g_P3h[off] = __float2half_rn(acc[z][dv]);
            else if (k == 0) g_P1[off] = acc[z][dv];
            else             g_P2[off] = acc[z][dv];
        }
}

// ---------------------------------------------------------------------------
// Trilinear. Grid (32, 8, 4): zq x [xq|ch] x b. CTA: M=128(4z x 32x), N=64(c).
// 8 warps = 4M x 2N; warp tile M32 x N32 (2 m-tiles x 4 n-tiles m16n8k16 f16).
// dv(4) x ck(2 x KC=128), cp.async double-buffered: p1/p2 fp32, p3 fp16.
// ---------------------------------------------------------------------------
#define KC    128
#define KPAD  132                       // fp32 row stride (p1, p2)
#define HPAD  136                       // fp16 row stride (p3)
#define OFF_P2F   (4 * KPAD)            // 528 floats
#define OFF_P3_B  ((OFF_P2F + 32 * KPAD) * 4)   // 19008 bytes
#define BUF_BYTES (OFF_P3_B + 64 * HPAD * 2)    // 36416 bytes
#define SMEM_BYTES (2 * BUF_BYTES)              // 72832

__global__ __launch_bounds__(256, 2) void tri_mma_kernel(float* __restrict__ out)
{
    extern __shared__ __align__(16) float sm[];

    const int tid  = threadIdx.x;
    const int wid  = tid >> 5;
    const int lane = tid & 31;
    const int grp  = lane >> 2;
    const int thr4 = lane & 3;

    const int zq = blockIdx.x;
    const int xq = blockIdx.y & 3;
    const int ch = blockIdx.y >> 2;
    const int b  = blockIdx.z;

    const int n0 = (wid >> 2) * 32;    // warp N offset
    const int zl = wid & 3;            // z row within CTA tile (uniform per warp)

    const uint32_t smu = (uint32_t)__cvta_generic_to_shared(sm);

    // stage s: dv = s>>1, ck = s&1, buffer = s&1
#define STAGE_FILL(s_)                                                          \
    {                                                                           \
        const int dv_ = (s_) >> 1, ck_ = (s_) & 1;                              \
        const uint32_t base = smu + ((s_) & 1) * BUF_BYTES;                     \
        const float*  p1b = g_P1  + ((size_t)((b * NDV + dv_) * NZ + zq * 4)) * NR + ck_ * KC;  \
        const float*  p2b = g_P2  + ((size_t)((b * NDV + dv_) * NZ + xq * 32)) * NR + ck_ * KC; \
        const __half* p3b = g_P3h + ((size_t)((b * NDV + dv_) * NZ + ch * 64)) * NR + ck_ * KC; \
        if (tid < 128) {                                                        \
            int r = tid >> 5, q = tid & 31;                                     \
            cp16(base + (r * KPAD + q * 4) * 4, p1b + r * NR + q * 4);          \
        }                                                                       \
        _Pragma("unroll")                                                       \
        for (int i = 0; i < 4; i++) {                                           \
            int g = i * 256 + tid, r = g >> 5, q = g & 31;                      \
            cp16(base + (OFF_P2F + r * KPAD + q * 4) * 4, p2b + r * NR + q * 4);\
        }                                                                       \
        _Pragma("unroll")                                                       \
        for (int i = 0; i < 4; i++) {                                           \
            int g = i * 256 + tid, r = g >> 4, q = g & 15;                      \
            cp16(base + OFF_P3_B + r * (HPAD * 2) + q * 16,                     \
                 p3b + r * NR + q * 8);                                         \
        }                                                                       \
    }

    float d[2][4][4];

    STAGE_FILL(0);
    cp_commit();

    for (int s = 0; s < 8; s++) {
        const int dv = s >> 1, ck = s & 1;
        if (s + 1 < 8) {
            STAGE_FILL(s + 1);
            cp_commit();
            cp_wait<1>();
        } else {
            cp_wait<0>();
        }
        __syncthreads();

        if (ck == 0) {
#pragma unroll
            for (int t = 0; t < 2; t++)
#pragma unroll
                for (int j = 0; j < 4; j++)
#pragma unroll
                    for (int i = 0; i < 4; i++) d[t][j][i] = 0.0f;
        }

        const float* p1s = sm + (s & 1) * (BUF_BYTES / 4);
        const float* p2s = p1s + OFF_P2F;
        const __half* p3s = (const __half*)((const char*)p1s + OFF_P3_B);

#pragma unroll
        for (int kk = 0; kk < KC / 16; kk++) {
            const int klo = kk * 16 + 2 * thr4;       // k, k+1  (low 8 of step)
            const int khi = klo + 8;                  // k+8, k+9

            float2 p1lo = *(const float2*)&p1s[zl * KPAD + klo];
            float2 p1hi = *(const float2*)&p1s[zl * KPAD + khi];

            uint32_t a[2][4];
#pragma unroll
            for (int t = 0; t < 2; t++) {
                const int x0 = 16 * t + grp;
                float2 v0lo = *(const float2*)&p2s[x0 * KPAD + klo];
                float2 v1lo = *(const float2*)&p2s[(x0 + 8) * KPAD + klo];
                float2 v0hi = *(const float2*)&p2s[x0 * KPAD + khi];
                float2 v1hi = *(const float2*)&p2s[(x0 + 8) * KPAD + khi];
                a[t][0] = packh2(p1lo.x * v0lo.x, p1lo.y * v0lo.y);
                a[t][1] = packh2(p1lo.x * v1lo.x, p1lo.y * v1lo.y);
                a[t][2] = packh2(p1hi.x * v0hi.x, p1hi.y * v0hi.y);
                a[t][3] = packh2(p1hi.x * v1hi.x, p1hi.y * v1hi.y);
            }
#pragma unroll
            for (int j = 0; j < 4; j++) {
                const int c = n0 + j * 8 + grp;
                uint32_t b0 = *(const uint32_t*)&p3s[c * HPAD + klo];
                uint32_t b1 = *(const uint32_t*)&p3s[c * HPAD + khi];
#pragma unroll
                for (int t = 0; t < 2; t++)
                    asm volatile(
                        "mma.sync.aligned.m16n8k16.row.col.f32.f16.f16.f32 "
                        "{%0,%1,%2,%3}, {%4,%5,%6,%7}, {%8,%9}, {%0,%1,%2,%3};"
                        : "+f"(d[t][j][0]), "+f"(d[t][j][1]),
                          "+f"(d[t][j][2]), "+f"(d[t][j][3])
                        : "r"(a[t][0]), "r"(a[t][1]), "r"(a[t][2]), "r"(a[t][3]),
                          "r"(b0), "r"(b1));
            }
        }

        if (ck == 1) {
            // Epilogue for this dv.
            const int z0g = zq * 4, x0g = xq * 32;
#pragma unroll
            for (int t = 0; t < 2; t++) {
                const int xa = 16 * t + grp;
                const size_t rb0 = ((((size_t)(b * NZ + z0g + zl)) * NZ
                                     + x0g + xa) * NZ) * NDV + dv;
                const size_t rb1 = ((((size_t)(b * NZ + z0g + zl)) * NZ
                                     + x0g + xa + 8) * NZ) * NDV + dv;
#pragma unroll
                for (int j = 0; j < 4; j++) {
                    const int cg = ch * 64 + n0 + j * 8 + thr4 * 2;
                    out[rb0 + (size_t)cg * NDV]       = d[t][j][0];
                    out[rb0 + (size_t)(cg + 1) * NDV] = d[t][j][1];
                    out[rb1 + (size_t)cg * NDV]       = d[t][j][2];
                    out[rb1 + (size_t)(cg + 1) * NDV] = d[t][j][3];
                }
            }
        }
        __syncthreads();
    }
#undef STAGE_FILL
}

// ---------------------------------------------------------------------------
extern "C" void kernel_launch(void* const* d_in, const int* in_sizes, int n_in,
                              void* d_out, int out_size)
{
    (void)in_sizes; (void)n_in; (void)out_size;
    const float* x1 = (const float*)d_in[0];
    const float* x2 = (const float*)d_in[1];
    const float* x3 = (const float*)d_in[2];
    const float* W1 = (const float*)d_in[3];
    const float* b1 = (const float*)d_in[4];
    const float* W2 = (const float*)d_in[5];
    const float* b2 = (const float*)d_in[6];
    const float* W3 = (const float*)d_in[7];
    const float* b3 = (const float*)d_in[8];
    float* out = (float*)d_out;

    static int attr_done = 0;
    if (!attr_done) {
        cudaFuncSetAttribute(tri_mma_kernel,
                             cudaFuncAttributeMaxDynamicSharedMemorySize, SMEM_BYTES);
        cudaFuncSetAttribute(proj_kernel,
                             cudaFuncAttributeMaxDynamicSharedMemorySize, PROJ_SMEM);
        attr_done = 1;
    }

    proj_kernel<<<dim3(32, NB, 3), 256, PROJ_SMEM>>>(x1, x2, x3, W1, b1, W2, b2, W3, b3);
    tri_mma_kernel<<<dim3(32, 8, NB), 256, SMEM_BYTES>>>(out);
}

// round 12
// speedup vs baseline: 1.8669x; 1.6321x over previous
#include <cuda_runtime.h>
#include <cuda_fp16.h>
#include <cstdint>

// FactorizedTrilinear: B=4, Z=X=C=128, D=V=2 (dv=4), IN=512, R=256
// proj: P_k[b][dv][row][e] = fp16( x_k[b,row,dv,:] @ W_k + b_k )
// tri:  out[b,z,x,c,dv] = sum_e (p1[z,e]*p2[x,e]) * p3[c,e] via
//       mma.sync.m16n8k16.f16 (A = hmul2(p1h, p2h), fp32 accum).
//       CTA = M128(4z x 32x) x N64(c), KC=128 double-buffered cp.async (fp16),
//       3 CTAs/SM. Per-dv results parked in a per-CTA dv-major global scratch
//       tile (dense float2 stores); fused tail re-reads the L2-hot tile and
//       writes out[] as fully dense float4 (4 dv per store).

#define NB  4
#define NZ  128
#define NIN 512
#define NR  256
#define NDV 4

__device__ __align__(16) __half g_P1h[NB * NDV * NZ * NR];
__device__ __align__(16) __half g_P2h[NB * NDV * NZ * NR];
__device__ __align__(16) __half g_P3h[NB * NDV * NZ * NR];
// Per-CTA scratch tiles: 1024 CTAs x 32768 floats (dv-major) = 128 MB.
__device__ __align__(16) float  g_S[1024 * 32768];

__device__ __forceinline__ void cp16(uint32_t dst, const void* src) {
    asm volatile("cp.async.cg.shared.global [%0], [%1], 16;"
                 :: "r"(dst), "l"(src) : "memory");
}
__device__ __forceinline__ void cp_commit() {
    asm volatile("cp.async.commit_group;" ::: "memory");
}
template <int N>
__device__ __forceinline__ void cp_wait() {
    asm volatile("cp.async.wait_group %0;" :: "n"(N) : "memory");
}
__device__ __forceinline__ uint32_t hmul2u(__half2 a, __half2 b) {
    __half2 r = __hmul2(a, b);
    return *(uint32_t*)&r;
}

// ---------------------------------------------------------------------------
// Projection: grid (32, 4, 3), 256 threads, 64 KB dynamic smem.
// Block = 4 z rows, r = tid. W streamed in 16-e chunks, cp.async double-buffered.
// All P stored fp16.
// ---------------------------------------------------------------------------
#define PROJ_SMEM ((4 * NIN * NDV + 2 * 16 * NR) * 4)   // 32KB + 32KB

__global__ __launch_bounds__(256) void proj_kernel(
    const float* __restrict__ x1, const float* __restrict__ x2, const float* __restrict__ x3,
    const float* __restrict__ W1, const float* __restrict__ bb1,
    const float* __restrict__ W2, const float* __restrict__ bb2,
    const float* __restrict__ W3, const float* __restrict__ bb3)
{
    extern __shared__ __align__(16) float psm[];
    float* xs = psm;                      // [z][e][dv] 4*512*4 floats
    float* ws = psm + 4 * NIN * NDV;      // 2 x [e16][r] 16*256 floats each

    const int z0 = blockIdx.x * 4;
    const int b  = blockIdx.y;
    const int k  = blockIdx.z;

    const float* x  = (k == 0) ? x1  : (k == 1) ? x2  : x3;
    const float* W  = (k == 0) ? W1  : (k == 1) ? W2  : W3;
    const float* bs = (k == 0) ? bb1 : (k == 1) ? bb2 : bb3;
    __half*      P  = (k == 0) ? g_P1h : (k == 1) ? g_P2h : g_P3h;

    const int tid = threadIdx.x;
    const uint32_t wsu = (uint32_t)__cvta_generic_to_shared(ws);

    const float* xg = x + ((size_t)(b * NZ + z0)) * NDV * NIN;
#pragma unroll
    for (int i = 0; i < 32; i++) {
        int idx = i * 256 + tid;
        int e   = idx & (NIN - 1);
        int zdv = idx >> 9;
        xs[((zdv >> 2) * NIN + e) * NDV + (zdv & 3)] = xg[zdv * NIN + e];
    }

#define WFILL(ec_)                                                      \
    {                                                                   \
        const float4* wg = (const float4*)(W + (ec_) * 16 * NR);        \
        uint32_t base = wsu + ((ec_) & 1) * (16 * NR * 4);              \
        _Pragma("unroll")                                               \
        for (int i = 0; i < 4; i++)                                     \
            cp16(base + (i * 256 + tid) * 16, wg + i * 256 + tid);      \
    }

    float acc[4][NDV];
    {
        float bv = bs[tid];
#pragma unroll
        for (int z = 0; z < 4; z++)
#pragma unroll
            for (int dv = 0; dv < NDV; dv++) acc[z][dv] = bv;
    }

    WFILL(0);
    cp_commit();

    for (int ec = 0; ec < NIN / 16; ec++) {
        if (ec + 1 < NIN / 16) {
            WFILL(ec + 1);
            cp_commit();
            cp_wait<1>();
        } else {
            cp_wait<0>();
        }
        __syncthreads();

        const float* w = ws + (ec & 1) * 16 * NR;
#pragma unroll
        for (int e16 = 0; e16 < 16; e16++) {
            float wv = w[e16 * NR + tid];
            int e = ec * 16 + e16;
#pragma unroll
            for (int z = 0; z < 4; z++) {
                float4 xv = *(const float4*)&xs[(z * NIN + e) * NDV];
                acc[z][0] = fmaf(xv.x, wv, acc[z][0]);
                acc[z][1] = fmaf(xv.y, wv, acc[z][1]);
                acc[z][2] = fmaf(xv.z, wv, acc[z][2]);
                acc[z][3] = fmaf(xv.w, wv, acc[z][3]);
            }
        }
        __syncthreads();
    }
#undef WFILL

#pragma unroll
    for (int z = 0; z < 4; z++)
#pragma unroll
        for (int dv = 0; dv < NDV; dv++)
            P[((size_t)((b * NDV + dv) * NZ + z0 + z)) * NR + tid] =
                __float2half_rn(acc[z][dv]);
}

// ---------------------------------------------------------------------------
// Trilinear. Grid (32, 8, 4): zq x [xq|ch] x b. CTA: M=128(4z x 32x), N=64(c).
// 8 warps = 4M x 2N; warp tile M32 x N32 (2 m-tiles x 4 n-tiles m16n8k16 f16).
// dv(4) x ck(2 x KC=128), fp16 staging double-buffered (54.4 KB, 3 CTAs/SM).
// ---------------------------------------------------------------------------
#define KC    128
#define HPAD  136                         // halves per row (h2 stride 68)
#define OFF_P2H  (4 * HPAD)               // 544 halves
#define OFF_P3H  (OFF_P2H + 32 * HPAD)    // 4896 halves
#define BUF_H    (OFF_P3H + 64 * HPAD)    // 13600 halves = 27200 B
#define SMEM_BYTES (2 * BUF_H * 2)        // 54400

__global__ __launch_bounds__(256, 3) void tri_mma_kernel(float* __restrict__ out)
{
    extern __shared__ __align__(16) __half2 smh[];

    const int tid  = threadIdx.x;
    const int wid  = tid >> 5;
    const int lane = tid & 31;
    const int grp  = lane >> 2;
    const int thr4 = lane & 3;

    const int zq = blockIdx.x;
    const int xq = blockIdx.y & 3;
    const int ch = blockIdx.y >> 2;
    const int b  = blockIdx.z;
    const int cta = (blockIdx.z * 8 + blockIdx.y) * 32 + blockIdx.x;

    const int n0 = (wid >> 2) * 32;    // warp N offset
    const int zl = wid & 3;            // z row within CTA tile (uniform per warp)

    const uint32_t smu = (uint32_t)__cvta_generic_to_shared(smh);
    float* sc = g_S + (size_t)cta * 32768;   // dv-major tile [dv][z4][x32][c64]

    // stage s: dv = s>>1, ck = s&1, buffer = s&1
#define STAGE_FILL(s_)                                                          \
    {                                                                           \
        const int dv_ = (s_) >> 1, ck_ = (s_) & 1;                              \
        const uint32_t base = smu + ((s_) & 1) * (BUF_H * 2);                   \
        const __half* p1b = g_P1h + ((size_t)((b * NDV + dv_) * NZ + zq * 4)) * NR + ck_ * KC;  \
        const __half* p2b = g_P2h + ((size_t)((b * NDV + dv_) * NZ + xq * 32)) * NR + ck_ * KC; \
        const __half* p3b = g_P3h + ((size_t)((b * NDV + dv_) * NZ + ch * 64)) * NR + ck_ * KC; \
        if (tid < 64) {                                                         \
            int r = tid >> 4, q = tid & 15;                                     \
            cp16(base + (r * HPAD + q * 8) * 2, p1b + r * NR + q * 8);          \
        }                                                                       \
        _Pragma("unroll")                                                       \
        for (int i = 0; i < 2; i++) {                                           \
            int g = i * 256 + tid, r = g >> 4, q = g & 15;                      \
            cp16(base + (OFF_P2H + r * HPAD + q * 8) * 2, p2b + r * NR + q * 8);\
        }                                                                       \
        _Pragma("unroll")                                                       \
        for (int i = 0; i < 4; i++) {                                           \
            int g = i * 256 + tid, r = g >> 4, q = g & 15;                      \
            cp16(base + (OFF_P3H + r * HPAD + q * 8) * 2, p3b + r * NR + q * 8);\
        }                                                                       \
    }

    float d[2][4][4];

    STAGE_FILL(0);
    cp_commit();

    for (int s = 0; s < 8; s++) {
        const int dv = s >> 1, ck = s & 1;
        if (s + 1 < 8) {
            STAGE_FILL(s + 1);
            cp_commit();
            cp_wait<1>();
        } else {
            cp_wait<0>();
        }
        __syncthreads();

        if (ck == 0) {
#pragma unroll
            for (int t = 0; t < 2; t++)
#pragma unroll
                for (int j = 0; j < 4; j++)
#pragma unroll
                    for (int i = 0; i < 4; i++) d[t][j][i] = 0.0f;
        }

        const __half2* p1s = smh + (s & 1) * BUF_H / 2;
        const __half2* p2s = p1s + OFF_P2H / 2;
        const __half2* p3s = p1s + OFF_P3H / 2;

#pragma unroll
        for (int kk = 0; kk < KC / 16; kk++) {
            const int k2lo = kk * 8 + thr4;   // half2 index of k = kk*16+2*thr4
            const int k2hi = k2lo + 4;

            __half2 p1lo = p1s[zl * 68 + k2lo];
            __half2 p1hi = p1s[zl * 68 + k2hi];

            uint32_t a[2][4];
#pragma unroll
            for (int t = 0; t < 2; t++) {
                const int x0 = 16 * t + grp;
                a[t][0] = hmul2u(p1lo, p2s[x0 * 68 + k2lo]);
                a[t][1] = hmul2u(p1lo, p2s[(x0 + 8) * 68 + k2lo]);
                a[t][2] = hmul2u(p1hi, p2s[x0 * 68 + k2hi]);
                a[t][3] = hmul2u(p1hi, p2s[(x0 + 8) * 68 + k2hi]);
            }
#pragma unroll
            for (int j = 0; j < 4; j++) {
                const int c = n0 + j * 8 + grp;
                uint32_t b0 = *(const uint32_t*)&p3s[c * 68 + k2lo];
                uint32_t b1 = *(const uint32_t*)&p3s[c * 68 + k2hi];
#pragma unroll
                for (int t = 0; t < 2; t++)
                    asm volatile(
                        "mma.sync.aligned.m16n8k16.row.col.f32.f16.f16.f32 "
                        "{%0,%1,%2,%3}, {%4,%5,%6,%7}, {%8,%9}, {%0,%1,%2,%3};"
                        : "+f"(d[t][j][0]), "+f"(d[t][j][1]),
                          "+f"(d[t][j][2]), "+f"(d[t][j][3])
                        : "r"(a[t][0]), "r"(a[t][1]), "r"(a[t][2]), "r"(a[t][3]),
                          "r"(b0), "r"(b1));
            }
        }

        if (ck == 1) {
            // Park this dv's tile in the dv-major scratch (dense float2 stores).
#pragma unroll
            for (int t = 0; t < 2; t++) {
                const int xa = 16 * t + grp;
#pragma unroll
                for (int j = 0; j < 4; j++) {
                    const int cgl = n0 + j * 8 + thr4 * 2;
                    int i0 = dv * 8192 + zl * 2048 + xa * 64 + cgl;
                    *(float2*)&sc[i0]            = make_float2(d[t][j][0], d[t][j][1]);
                    *(float2*)&sc[i0 + 8 * 64]   = make_float2(d[t][j][2], d[t][j][3]);
                }
            }
        }
        __syncthreads();
    }
#undef STAGE_FILL

    // Fused tail: re-read the (L2-hot) scratch tile and write out[] as dense
    // float4 (all 4 dv per store). 8192 positions, 32 per thread, coalesced.
    float4* o4 = (float4*)out;
#pragma unroll
    for (int i = 0; i < 32; i++) {
        int f   = i * 256 + tid;       // 0..8191
        int c   = f & 63;
        int xa  = (f >> 6) & 31;
        int zz  = f >> 11;             // 0..3
        int p   = zz * 2048 + xa * 64 + c;
        float4 v;
        v.x = sc[p];
        v.y = sc[p + 8192];
        v.z = sc[p + 16384];
        v.w = sc[p + 24576];
        size_t oi = (((size_t)(b * NZ + zq * 4 + zz) * NZ + xq * 32 + xa) * NZ
                     + ch * 64 + c);
        o4[oi] = v;
    }
}

// ---------------------------------------------------------------------------
extern "C" void kernel_launch(void* const* d_in, const int* in_sizes, int n_in,
                              void* d_out, int out_size)
{
    (void)in_sizes; (void)n_in; (void)out_size;
    const float* x1 = (const float*)d_in[0];
    const float* x2 = (const float*)d_in[1];
    const float* x3 = (const float*)d_in[2];
    const float* W1 = (const float*)d_in[3];
    const float* b1 = (const float*)d_in[4];
    const float* W2 = (const float*)d_in[5];
    const float* b2 = (const float*)d_in[6];
    const float* W3 = (const float*)d_in[7];
    const float* b3 = (const float*)d_in[8];
    float* out = (float*)d_out;

    static int attr_done = 0;
    if (!attr_done) {
        cudaFuncSetAttribute(tri_mma_kernel,
                             cudaFuncAttributeMaxDynamicSharedMemorySize, SMEM_BYTES);
        cudaFuncSetAttribute(proj_kernel,
                             cudaFuncAttributeMaxDynamicSharedMemorySize, PROJ_SMEM);
        attr_done = 1;
    }

    proj_kernel<<<dim3(32, NB, 3), 256, PROJ_SMEM>>>(x1, x2, x3, W1, b1, W2, b2, W3, b3);
    tri_mma_kernel<<<dim3(32, 8, NB), 256, SMEM_BYTES>>>(out);
}